// round 15
// baseline (speedup 1.0000x reference)
#include <cuda_runtime.h>
#include <cuda_fp16.h>
#include <cstdint>

#define TPB  256
#define TILE 128
#define WSTR 136   // weight smem row stride (elems), 128 cols padded
#define ASTR 136   // activation smem row stride (elems)
#define PSTR 72    // pos row stride (64 cols padded)
#define VSTR 40    // view row stride (32 cols padded)
#define WCHUNK 17408   // one 64-row weight chunk in smem bytes

// Single-fp16 weight scratch, row-major [1184][136], filled by prep kernel.
// Stage rows:  0 d1_W0(0,64)  1 d1_W1(64,128)  2 d1_W2(192,128)
//  3 d2_W0a(320,64)  4 d2_W0b(384,128)  5 d2_W1(512,128)  6 d2_W2(640,128)
//  7 d2_W3f(768,128) 8 c_W0a(896,32)   9 c_W0b(928,128) 10 c_W1p(1056,128)
__device__ __half g_w[1184 * WSTR];
__device__ float g_wd[128];

__constant__ int c_offs[11] = {0, 64, 192, 320, 384, 512, 640, 768, 896, 928, 1056};

// 19 weight chunks of <=64 K-rows, streamed through 2 half-buffers
__constant__ int ch_row[19] = {0, 64, 128, 192, 256, 320, 384, 448, 512, 576,
                               640, 704, 768, 832, 896, 928, 992, 1056, 1120};
__constant__ int ch_nr[19]  = {64, 64, 64, 64, 64, 64, 64, 64, 64, 64,
                               64, 64, 64, 64, 32, 64, 64, 64, 64};
__constant__ int st_nch[11] = {1, 2, 2, 1, 2, 2, 2, 2, 1, 2, 2};

__global__ void prep_kernel(const float* __restrict__ d1_W0, const float* __restrict__ d1_W1,
                            const float* __restrict__ d1_W2, const float* __restrict__ d2_W0,
                            const float* __restrict__ d2_W1, const float* __restrict__ d2_W2,
                            const float* __restrict__ d2_W3, const float* __restrict__ c_W0,
                            const float* __restrict__ c_W1) {
    int prow = blockIdx.x;      // 0..1183
    int n = threadIdx.x;        // 0..135
    int li = 0;
#pragma unroll
    for (int i = 1; i < 11; i++)
        if (prow >= c_offs[i]) li = i;
    int k = prow - c_offs[li];
    float v = 0.f;
    if (n < 128) {
        switch (li) {
            case 0: if (k < 63) v = d1_W0[k * 128 + n]; break;
            case 1: v = d1_W1[k * 128 + n]; break;
            case 2: v = d1_W2[k * 128 + n]; break;
            case 3: if (k < 63) v = d2_W0[k * 128 + n]; break;
            case 4: v = d2_W0[(63 + k) * 128 + n]; break;
            case 5: v = d2_W1[k * 128 + n]; break;
            case 6: v = d2_W2[k * 128 + n]; break;
            case 7: v = d2_W3[k * 129 + 1 + n]; break;          // feature cols
            case 8: if (k < 27) v = c_W0[k * 128 + n]; break;
            case 9: v = c_W0[(27 + k) * 128 + n]; break;
            case 10: if (n < 3) v = c_W1[k * 3 + n]; break;
        }
    }
    g_w[prow * WSTR + n] = __float2half_rn(v);
    if (prow == 0 && n < 128) g_wd[n] = d2_W3[n * 129];         // density col
}

__device__ __forceinline__ uint32_t sptr(const void* p) {
    return (uint32_t)__cvta_generic_to_shared(p);
}
__device__ __forceinline__ void ldm4(uint32_t& r0, uint32_t& r1, uint32_t& r2, uint32_t& r3, uint32_t a) {
    asm volatile("ldmatrix.sync.aligned.m8n8.x4.shared.b16 {%0,%1,%2,%3}, [%4];"
                 : "=r"(r0), "=r"(r1), "=r"(r2), "=r"(r3) : "r"(a));
}
__device__ __forceinline__ void ldm4t(uint32_t& r0, uint32_t& r1, uint32_t& r2, uint32_t& r3, uint32_t a) {
    asm volatile("ldmatrix.sync.aligned.m8n8.x4.trans.shared.b16 {%0,%1,%2,%3}, [%4];"
                 : "=r"(r0), "=r"(r1), "=r"(r2), "=r"(r3) : "r"(a));
}
__device__ __forceinline__ void ldm2t(uint32_t& r0, uint32_t& r1, uint32_t a) {
    asm volatile("ldmatrix.sync.aligned.m8n8.x2.trans.shared.b16 {%0,%1}, [%2];"
                 : "=r"(r0), "=r"(r1) : "r"(a));
}
__device__ __forceinline__ void mma_f16(float* c, const uint32_t* a, uint32_t b0, uint32_t b1) {
    asm volatile("mma.sync.aligned.m16n8k16.row.col.f32.f16.f16.f32 "
                 "{%0,%1,%2,%3}, {%4,%5,%6,%7}, {%8,%9}, {%0,%1,%2,%3};"
                 : "+f"(c[0]), "+f"(c[1]), "+f"(c[2]), "+f"(c[3])
                 : "r"(a[0]), "r"(a[1]), "r"(a[2]), "r"(a[3]), "r"(b0), "r"(b1));
}
__device__ __forceinline__ void cpa16cg(uint32_t s, const void* g) {
    asm volatile("cp.async.cg.shared.global [%0], [%1], 16;" :: "r"(s), "l"(g));
}

// -------- SMEM map (bytes): 2 half-size weight chunk buffers + SMEM activations --------
#define SM_W     0                       // 2 x 17408 chunk buffers
#define SM_ACT   34816                   // 34816 (128 x 136 x fp16)
#define SM_POS   69632                   // 128 x 72 x fp16 = 18432
#define SM_VIEW  88064                   // 128 x 40 x fp16 = 10240
#define SM_WD    98304                   // 128 f32
#define SM_DENS  98816                   // 2 x 128 f32 = 1024
#define SM_OSTG  99840                   // 128 x 4 f32
#define SMEM_TOTAL 101888

__global__ void __launch_bounds__(TPB, 2)
nerf_main(const float* __restrict__ x, float* __restrict__ out) {
    extern __shared__ __align__(16) char smem[];
    const uint32_t sb = sptr(smem);
    __half* posH  = (__half*)(smem + SM_POS);
    __half* viewH = (__half*)(smem + SM_VIEW);
    float* swd  = (float*)(smem + SM_WD);
    float* dens = (float*)(smem + SM_DENS);
    float* ostg = (float*)(smem + SM_OSTG);

    const int tid  = threadIdx.x;
    const int lane = tid & 31;
    const int warp = tid >> 5;
    const int group = warp >> 1;         // 0..3: rows group*32 .. +31
    const int half  = warp & 1;          // output-column half (0: cols 0-63, 1: 64-127)
    const int r0    = group * 32;
    const int npb   = half * 4;          // np base (16-col units)
    const size_t tile = blockIdx.x;

    auto loadChunk = [&](int c) {        // into buffer c&1
        const __half* g = g_w + ch_row[c] * WSTR;
        const uint32_t b = sb + SM_W + (uint32_t)(c & 1) * WCHUNK;
        const int n16 = ch_nr[c] * 17;                  // 16B transfers
        for (int i = tid; i < n16; i += TPB)
            cpa16cg(b + i * 16, g + i * 8);
        asm volatile("cp.async.commit_group;" ::: "memory");
    };

    // chunk 0 in flight during input staging
    loadChunk(0);

    // zero pos/view buffers (padded cols must be 0), load density weights
    {
        uint4* pz = (uint4*)(smem + SM_POS);
        for (int i = tid; i < (SM_WD - SM_POS) / 16; i += TPB)
            pz[i] = make_uint4(0, 0, 0, 0);
        if (tid < 128) swd[tid] = g_wd[tid];
    }
    __syncthreads();
    {
        const float* xt = x + tile * (size_t)(TILE * 90);
        for (int i = tid; i < TILE * 90; i += TPB) {
            int row = i / 90, c = i - row * 90;
            __half h = __float2half_rn(xt[i]);
            if (c < 63) posH[row * PSTR + c] = h;
            else        viewH[row * VSTR + c - 63] = h;
        }
    }
    __syncthreads();

    // acc tile t = mt*8 + npl*2 + h : rows r0+mt*16, cols half*64 + npl*16 + 8h
    float acc[16][4];
    const int krow = lane & 15;
    const int nsel = (lane >> 4) * 8;
    const int rq = lane >> 2, m = lane & 3;
    const int row0 = r0 + rq;
    const uint32_t ab = sb + SM_ACT;

    auto zero_acc = [&]() {
#pragma unroll
        for (int t = 0; t < 16; t++)
#pragma unroll
            for (int j = 0; j < 4; j++) acc[t][j] = 0.f;
    };
    auto relu_acc = [&]() {
#pragma unroll
        for (int t = 0; t < 16; t++)
#pragma unroll
            for (int j = 0; j < 4; j++) acc[t][j] = fmaxf(acc[t][j], 0.f);
    };
    // accumulators -> fp16 activations in SMEM (warp's 32x64 quadrant)
    auto act_store = [&](bool dorelu) {
#pragma unroll
        for (int mt = 0; mt < 2; mt++)
#pragma unroll
            for (int npl = 0; npl < 4; npl++)
#pragma unroll
                for (int h = 0; h < 2; h++) {
                    const int t = mt * 8 + npl * 2 + h;
                    float v0 = acc[t][0], v1 = acc[t][1], v2 = acc[t][2], v3 = acc[t][3];
                    if (dorelu) {
                        v0 = fmaxf(v0, 0.f); v1 = fmaxf(v1, 0.f);
                        v2 = fmaxf(v2, 0.f); v3 = fmaxf(v3, 0.f);
                    }
                    __half2 h01 = __floats2half2_rn(v0, v1);
                    __half2 h23 = __floats2half2_rn(v2, v3);
                    const uint32_t co = (uint32_t)(half * 64 + npl * 16 + 8 * h + 2 * m) * 2;
                    const int rA = row0 + mt * 16;
                    asm volatile("st.shared.b32 [%0], %1;"
                                 :: "r"(ab + (uint32_t)(rA * ASTR) * 2 + co),
                                    "r"(reinterpret_cast<uint32_t&>(h01)) : "memory");
                    asm volatile("st.shared.b32 [%0], %1;"
                                 :: "r"(ab + (uint32_t)((rA + 8) * ASTR) * 2 + co),
                                    "r"(reinterpret_cast<uint32_t&>(h23)) : "memory");
                }
    };
    // unified MMA: M=32 x N=64 warp tile; A via ldmatrix at global kt=ktbase+ktl,
    // weights at LOCAL rows ktl within the chunk buffer wbuf.
    auto mma_src = [&](uint32_t bA, int astr, int ktbase, int KT, uint32_t wbuf) {
        const int arow = r0 + krow;
        for (int ktl = 0; ktl < KT; ktl++) {
            const int kt = ktbase + ktl;
            uint32_t ta0[4], ta1[4];
            uint32_t ao = (uint32_t)(arow * astr + kt * 16 + nsel) * 2;
            ldm4(ta0[0], ta0[1], ta0[2], ta0[3], bA + ao);
            ldm4(ta1[0], ta1[1], ta1[2], ta1[3], bA + ao + (uint32_t)(16 * astr) * 2);
#pragma unroll
            for (int npl = 0; npl < 4; npl++) {
                uint32_t b0, b1, b2, b3;
                uint32_t wo = (uint32_t)((ktl * 16 + krow) * WSTR + (npb + npl) * 16 + nsel) * 2;
                ldm4t(b0, b1, b2, b3, wbuf + wo);
                mma_f16(acc[npl * 2],     ta0, b0, b1);
                mma_f16(acc[npl * 2 + 1], ta0, b2, b3);
                mma_f16(acc[8 + npl * 2],     ta1, b0, b1);
                mma_f16(acc[8 + npl * 2 + 1], ta1, b2, b3);
            }
        }
    };

    zero_acc();
    int c = 0;
    for (int st = 0; st < 11; st++) {
        // ---- stage-boundary epilogue (chunk c, first of this stage, is in flight) ----
        if (st == 7) {                      // density partials from relu'd h5 (this half)
            relu_acc();
            float d00 = 0.f, d01 = 0.f, d10 = 0.f, d11 = 0.f;
#pragma unroll
            for (int npl = 0; npl < 4; npl++)
#pragma unroll
                for (int h = 0; h < 2; h++) {
                    const int col = half * 64 + npl * 16 + 8 * h + 2 * m;
                    const float w0 = swd[col], w1 = swd[col + 1];
                    const int t0 = npl * 2 + h, t1 = 8 + npl * 2 + h;
                    d00 += acc[t0][0] * w0 + acc[t0][1] * w1;
                    d01 += acc[t0][2] * w0 + acc[t0][3] * w1;
                    d10 += acc[t1][0] * w0 + acc[t1][1] * w1;
                    d11 += acc[t1][2] * w0 + acc[t1][3] * w1;
                }
            d00 += __shfl_xor_sync(~0u, d00, 1); d00 += __shfl_xor_sync(~0u, d00, 2);
            d01 += __shfl_xor_sync(~0u, d01, 1); d01 += __shfl_xor_sync(~0u, d01, 2);
            d10 += __shfl_xor_sync(~0u, d10, 1); d10 += __shfl_xor_sync(~0u, d10, 2);
            d11 += __shfl_xor_sync(~0u, d11, 1); d11 += __shfl_xor_sync(~0u, d11, 2);
            if (m == 0) {
                dens[half * 128 + row0]      = d00;
                dens[half * 128 + row0 + 8]  = d01;
                dens[half * 128 + row0 + 16] = d10;
                dens[half * 128 + row0 + 24] = d11;
            }
        }
        if (st >= 1 && st != 4 && st != 9) {
            act_store(st <= 6 || st == 10); // relu except feature/out2 paths (st7 pre-relu'd)
            if (st != 10) zero_acc();
        }
        if (st == 10) {                     // rgb accumulators live in acc[0], acc[1]
#pragma unroll
            for (int j = 0; j < 4; j++) { acc[0][j] = 0.f; acc[1][j] = 0.f; }
        }

        const int nch = st_nch[st];
        for (int j = 0; j < nch; j++, c++) {
            if (c + 1 < 19) {
                loadChunk(c + 1);           // buffer (c+1)&1: chunk c-1's, done last iter
                asm volatile("cp.async.wait_group 1;" ::: "memory");
            } else {
                asm volatile("cp.async.wait_group 0;" ::: "memory");
            }
            __syncthreads();                // chunk c + act/dens visible to all
            if (st == 7 && j == 0 && half == 0 && m == 0) {  // combine density halves
#pragma unroll
                for (int rr = 0; rr < 4; rr++) {
                    const int r = row0 + rr * 8;
                    ostg[r * 4 + 3] = dens[r] + dens[128 + r];
                }
            }
            const uint32_t wbuf = sb + SM_W + (uint32_t)(c & 1) * WCHUNK;
            if (st == 0 || st == 3)      mma_src(sptr(posH), PSTR, 0, 4, wbuf);
            else if (st == 8)            mma_src(sptr(viewH), VSTR, 0, 2, wbuf);
            else if (st == 10) {            // rgb: K chunk, N=8 (3 real), half 0 only
                if (half == 0) {
                    const int arow = r0 + krow;
#pragma unroll
                    for (int ktl = 0; ktl < 4; ktl++) {
                        const int kt = 4 * j + ktl;
                        uint32_t ta0[4], ta1[4];
                        uint32_t ao = (uint32_t)(arow * ASTR + kt * 16 + nsel) * 2;
                        ldm4(ta0[0], ta0[1], ta0[2], ta0[3], ab + ao);
                        ldm4(ta1[0], ta1[1], ta1[2], ta1[3], ab + ao + (uint32_t)(16 * ASTR) * 2);
                        uint32_t b0, b1;
                        uint32_t wo = (uint32_t)((ktl * 16 + krow) * WSTR) * 2;
                        ldm2t(b0, b1, wbuf + wo);
                        mma_f16(acc[0], ta0, b0, b1);
                        mma_f16(acc[1], ta1, b0, b1);
                    }
                }
            } else                        mma_src(ab, ASTR, 4 * j, 4, wbuf);
            __syncthreads();                // all done with buffer c&1 before overwrite
        }
    }

    // rgb output from acc[0] (rows r0..r0+15) / acc[1] (rows r0+16..r0+31)
    if (half == 0) {
        if (2 * m < 3) {
            ostg[row0 * 4 + 2 * m]        = acc[0][0];
            ostg[(row0 + 8) * 4 + 2 * m]  = acc[0][2];
            ostg[(row0 + 16) * 4 + 2 * m] = acc[1][0];
            ostg[(row0 + 24) * 4 + 2 * m] = acc[1][2];
        }
        if (2 * m + 1 < 3) {
            ostg[row0 * 4 + 2 * m + 1]        = acc[0][1];
            ostg[(row0 + 8) * 4 + 2 * m + 1]  = acc[0][3];
            ostg[(row0 + 16) * 4 + 2 * m + 1] = acc[1][1];
            ostg[(row0 + 24) * 4 + 2 * m + 1] = acc[1][3];
        }
    }

    __syncthreads();
    if (tid < TILE)
        ((float4*)out)[tile * TILE + tid] = ((const float4*)ostg)[tid];
}

extern "C" void kernel_launch(void* const* d_in, const int* in_sizes, int n_in,
                              void* d_out, int out_size) {
    const float* x     = (const float*)d_in[0];
    const float* d1_W0 = (const float*)d_in[1];
    const float* d1_W1 = (const float*)d_in[2];
    const float* d1_W2 = (const float*)d_in[3];
    const float* d2_W0 = (const float*)d_in[4];
    const float* d2_W1 = (const float*)d_in[5];
    const float* d2_W2 = (const float*)d_in[6];
    const float* d2_W3 = (const float*)d_in[7];
    const float* c_W0  = (const float*)d_in[8];
    const float* c_W1  = (const float*)d_in[9];
    const int N = in_sizes[0] / 90;

    prep_kernel<<<1184, WSTR>>>(d1_W0, d1_W1, d1_W2, d2_W0, d2_W1, d2_W2, d2_W3, c_W0, c_W1);
    cudaFuncSetAttribute(nerf_main, cudaFuncAttributeMaxDynamicSharedMemorySize, SMEM_TOTAL);
    nerf_main<<<N / TILE, TPB, SMEM_TOTAL>>>(x, (float*)d_out);
}

// round 16
// speedup vs baseline: 1.6011x; 1.6011x over previous
#include <cuda_runtime.h>
#include <cuda_fp16.h>
#include <cstdint>

#define TPB  256
#define TILE 128
#define WSTR 136   // weight smem row stride (elems), 128 cols padded
#define ASTR 136   // activation smem row stride (elems)
#define PSTR 72    // pos row stride (64 cols padded)
#define VSTR 40    // view row stride (32 cols padded)

// Single-fp16 weight scratch, row-major [1184][136], filled by prep kernel.
// Stage rows:  0 d1_W0(0,64)  1 d1_W1(64,128)  2 d1_W2(192,128)
//  3 d2_W0a(320,64)  4 d2_W0b(384,128)  5 d2_W1(512,128)  6 d2_W2(640,128)
//  7 d2_W3f(768,128) 8 c_W0a(896,32)   9 c_W0b(928,128) 10 c_W1p(1056,128)
__device__ __half g_w[1184 * WSTR];
__device__ float g_wd[128];

__constant__ int c_offs[11] = {0, 64, 192, 320, 384, 512, 640, 768, 896, 928, 1056};
__constant__ int c_rows[11] = {64, 128, 128, 64, 128, 128, 128, 128, 32, 128, 128};

__global__ void prep_kernel(const float* __restrict__ d1_W0, const float* __restrict__ d1_W1,
                            const float* __restrict__ d1_W2, const float* __restrict__ d2_W0,
                            const float* __restrict__ d2_W1, const float* __restrict__ d2_W2,
                            const float* __restrict__ d2_W3, const float* __restrict__ c_W0,
                            const float* __restrict__ c_W1) {
    int prow = blockIdx.x;      // 0..1183
    int n = threadIdx.x;        // 0..135
    int li = 0;
#pragma unroll
    for (int i = 1; i < 11; i++)
        if (prow >= c_offs[i]) li = i;
    int k = prow - c_offs[li];
    float v = 0.f;
    if (n < 128) {
        switch (li) {
            case 0: if (k < 63) v = d1_W0[k * 128 + n]; break;
            case 1: v = d1_W1[k * 128 + n]; break;
            case 2: v = d1_W2[k * 128 + n]; break;
            case 3: if (k < 63) v = d2_W0[k * 128 + n]; break;
            case 4: v = d2_W0[(63 + k) * 128 + n]; break;
            case 5: v = d2_W1[k * 128 + n]; break;
            case 6: v = d2_W2[k * 128 + n]; break;
            case 7: v = d2_W3[k * 129 + 1 + n]; break;          // feature cols
            case 8: if (k < 27) v = c_W0[k * 128 + n]; break;
            case 9: v = c_W0[(27 + k) * 128 + n]; break;
            case 10: if (n < 3) v = c_W1[k * 3 + n]; break;
        }
    }
    g_w[prow * WSTR + n] = __float2half_rn(v);
    if (prow == 0 && n < 128) g_wd[n] = d2_W3[n * 129];         // density col
}

__device__ __forceinline__ uint32_t sptr(const void* p) {
    return (uint32_t)__cvta_generic_to_shared(p);
}
__device__ __forceinline__ void ldm4(uint32_t& r0, uint32_t& r1, uint32_t& r2, uint32_t& r3, uint32_t a) {
    asm volatile("ldmatrix.sync.aligned.m8n8.x4.shared.b16 {%0,%1,%2,%3}, [%4];"
                 : "=r"(r0), "=r"(r1), "=r"(r2), "=r"(r3) : "r"(a));
}
__device__ __forceinline__ void ldm4t(uint32_t& r0, uint32_t& r1, uint32_t& r2, uint32_t& r3, uint32_t a) {
    asm volatile("ldmatrix.sync.aligned.m8n8.x4.trans.shared.b16 {%0,%1,%2,%3}, [%4];"
                 : "=r"(r0), "=r"(r1), "=r"(r2), "=r"(r3) : "r"(a));
}
__device__ __forceinline__ void ldm2t(uint32_t& r0, uint32_t& r1, uint32_t a) {
    asm volatile("ldmatrix.sync.aligned.m8n8.x2.trans.shared.b16 {%0,%1}, [%2];"
                 : "=r"(r0), "=r"(r1) : "r"(a));
}
__device__ __forceinline__ void mma_f16(float* c, const uint32_t* a, uint32_t b0, uint32_t b1) {
    asm volatile("mma.sync.aligned.m16n8k16.row.col.f32.f16.f16.f32 "
                 "{%0,%1,%2,%3}, {%4,%5,%6,%7}, {%8,%9}, {%0,%1,%2,%3};"
                 : "+f"(c[0]), "+f"(c[1]), "+f"(c[2]), "+f"(c[3])
                 : "r"(a[0]), "r"(a[1]), "r"(a[2]), "r"(a[3]), "r"(b0), "r"(b1));
}
__device__ __forceinline__ void cpa16cg(uint32_t s, const void* g) {
    asm volatile("cp.async.cg.shared.global [%0], [%1], 16;" :: "r"(s), "l"(g));
}

// -------- SMEM map (bytes): single weight buffer + SMEM activations --------
#define SM_W     0                       // 34816 (128 x 136 x fp16)
#define SM_ACT   34816                   // 34816 (128 x 136 x fp16)
#define SM_POS   69632                   // 128 x 72 x fp16 = 18432
#define SM_VIEW  88064                   // 128 x 40 x fp16 = 10240
#define SM_WD    98304                   // 128 f32
#define SM_DENS  98816                   // 2 x 128 f32 = 1024
#define SM_OSTG  99840                   // 128 x 4 f32
#define SMEM_TOTAL 101888

__global__ void __launch_bounds__(TPB, 2)
nerf_main(const float* __restrict__ x, float* __restrict__ out) {
    extern __shared__ __align__(16) char smem[];
    const uint32_t sb = sptr(smem);
    __half* posH  = (__half*)(smem + SM_POS);
    __half* viewH = (__half*)(smem + SM_VIEW);
    float* swd  = (float*)(smem + SM_WD);
    float* dens = (float*)(smem + SM_DENS);
    float* ostg = (float*)(smem + SM_OSTG);

    const int tid  = threadIdx.x;
    const int lane = tid & 31;
    const int warp = tid >> 5;
    const int group = warp >> 1;         // 0..3: rows group*32 .. +31
    const int half  = warp & 1;          // output-column half (0: cols 0-63, 1: 64-127)
    const int r0    = group * 32;
    const int npb   = half * 4;          // np base (16-col units)
    const size_t tile = blockIdx.x;

    auto loadW = [&](int st) {
        const __half* g = g_w + c_offs[st] * WSTR;
        const int chunks = c_rows[st] * 17;             // 16B chunks
        for (int i = tid; i < chunks; i += TPB)
            cpa16cg(sb + SM_W + i * 16, g + i * 8);
        asm volatile("cp.async.commit_group;" ::: "memory");
    };

    // stage-0 weights in flight during input staging
    loadW(0);

    // zero pos/view buffers (padded cols must be 0), load density weights
    {
        uint4* pz = (uint4*)(smem + SM_POS);
        for (int i = tid; i < (SM_WD - SM_POS) / 16; i += TPB)
            pz[i] = make_uint4(0, 0, 0, 0);
        if (tid < 128) swd[tid] = g_wd[tid];
    }
    __syncthreads();
    {
        const float* xt = x + tile * (size_t)(TILE * 90);
        for (int i = tid; i < TILE * 90; i += TPB) {
            int row = i / 90, c = i - row * 90;
            __half h = __float2half_rn(xt[i]);
            if (c < 63) posH[row * PSTR + c] = h;
            else        viewH[row * VSTR + c - 63] = h;
        }
    }
    asm volatile("cp.async.wait_group 0;" ::: "memory");
    __syncthreads();

    // acc tile t = mt*8 + npl*2 + h : rows r0+mt*16, cols half*64 + npl*16 + 8h
    float acc[16][4];
    const int krow = lane & 15;
    const int nsel = (lane >> 4) * 8;
    const int rq = lane >> 2, m = lane & 3;
    const int row0 = r0 + rq;
    const uint32_t ab = sb + SM_ACT;
    // warp-constant LDSM address bases (fold per-kt offsets into immediates)
    const uint32_t wbase = sb + SM_W + (uint32_t)(krow * WSTR + npb * 16 + nsel) * 2;
    const int arowk = r0 + krow;

    auto zero_acc = [&]() {
#pragma unroll
        for (int t = 0; t < 16; t++)
#pragma unroll
            for (int j = 0; j < 4; j++) acc[t][j] = 0.f;
    };
    auto relu_acc = [&]() {
#pragma unroll
        for (int t = 0; t < 16; t++)
#pragma unroll
            for (int j = 0; j < 4; j++) acc[t][j] = fmaxf(acc[t][j], 0.f);
    };
    // accumulators -> fp16 activations in SMEM (warp's 32x64 quadrant)
    auto act_store = [&](bool dorelu) {
#pragma unroll
        for (int mt = 0; mt < 2; mt++)
#pragma unroll
            for (int npl = 0; npl < 4; npl++)
#pragma unroll
                for (int h = 0; h < 2; h++) {
                    const int t = mt * 8 + npl * 2 + h;
                    float v0 = acc[t][0], v1 = acc[t][1], v2 = acc[t][2], v3 = acc[t][3];
                    if (dorelu) {
                        v0 = fmaxf(v0, 0.f); v1 = fmaxf(v1, 0.f);
                        v2 = fmaxf(v2, 0.f); v3 = fmaxf(v3, 0.f);
                    }
                    __half2 h01 = __floats2half2_rn(v0, v1);
                    __half2 h23 = __floats2half2_rn(v2, v3);
                    const uint32_t co = (uint32_t)(half * 64 + npl * 16 + 8 * h + 2 * m) * 2;
                    const int rA = row0 + mt * 16;
                    asm volatile("st.shared.b32 [%0], %1;"
                                 :: "r"(ab + (uint32_t)(rA * ASTR) * 2 + co),
                                    "r"(reinterpret_cast<uint32_t&>(h01)) : "memory");
                    asm volatile("st.shared.b32 [%0], %1;"
                                 :: "r"(ab + (uint32_t)((rA + 8) * ASTR) * 2 + co),
                                    "r"(reinterpret_cast<uint32_t&>(h23)) : "memory");
                }
    };
    // unified MMA: M=32 (2 m16 frags), N=64 (this warp's half); KT/astr compile-time
    auto mma_body = [&]<int KT, int astrC>(uint32_t bA) {
        const uint32_t abase = bA + (uint32_t)(arowk * astrC + nsel) * 2;
#pragma unroll
        for (int kt = 0; kt < KT; kt++) {
            uint32_t ta0[4], ta1[4];
            const uint32_t ao = abase + (uint32_t)(kt * 16) * 2;
            ldm4(ta0[0], ta0[1], ta0[2], ta0[3], ao);
            ldm4(ta1[0], ta1[1], ta1[2], ta1[3], ao + (uint32_t)(16 * astrC) * 2);
#pragma unroll
            for (int npl = 0; npl < 4; npl++) {
                uint32_t b0, b1, b2, b3;
                const uint32_t wo = wbase + (uint32_t)(kt * 16 * WSTR + npl * 16) * 2;
                ldm4t(b0, b1, b2, b3, wo);
                mma_f16(acc[npl * 2],     ta0, b0, b1);
                mma_f16(acc[npl * 2 + 1], ta0, b2, b3);
                mma_f16(acc[8 + npl * 2],     ta1, b0, b1);
                mma_f16(acc[8 + npl * 2 + 1], ta1, b2, b3);
            }
        }
    };

    zero_acc();
    for (int st = 0; st < 11; st++) {
        __syncthreads();                    // all warps done with W + act of prev stage
        if (st >= 1) loadW(st);             // into the single buffer (st0 preloaded)

        // ---- stage-boundary register/SMEM work (overlaps in-flight cp.async) ----
        if (st == 7) {                      // density partials from relu'd h5 (this half)
            relu_acc();
            float d00 = 0.f, d01 = 0.f, d10 = 0.f, d11 = 0.f;
#pragma unroll
            for (int npl = 0; npl < 4; npl++)
#pragma unroll
                for (int h = 0; h < 2; h++) {
                    const int col = half * 64 + npl * 16 + 8 * h + 2 * m;
                    const float w0 = swd[col], w1 = swd[col + 1];
                    const int t0 = npl * 2 + h, t1 = 8 + npl * 2 + h;
                    d00 += acc[t0][0] * w0 + acc[t0][1] * w1;
                    d01 += acc[t0][2] * w0 + acc[t0][3] * w1;
                    d10 += acc[t1][0] * w0 + acc[t1][1] * w1;
                    d11 += acc[t1][2] * w0 + acc[t1][3] * w1;
                }
            d00 += __shfl_xor_sync(~0u, d00, 1); d00 += __shfl_xor_sync(~0u, d00, 2);
            d01 += __shfl_xor_sync(~0u, d01, 1); d01 += __shfl_xor_sync(~0u, d01, 2);
            d10 += __shfl_xor_sync(~0u, d10, 1); d10 += __shfl_xor_sync(~0u, d10, 2);
            d11 += __shfl_xor_sync(~0u, d11, 1); d11 += __shfl_xor_sync(~0u, d11, 2);
            if (m == 0) {
                dens[half * 128 + row0]      = d00;
                dens[half * 128 + row0 + 8]  = d01;
                dens[half * 128 + row0 + 16] = d10;
                dens[half * 128 + row0 + 24] = d11;
            }
        }
        if (st >= 1 && st != 4 && st != 9) {
            act_store(st <= 6 || st == 10); // relu except feature/out2 paths (st7 pre-relu'd)
            if (st != 10) zero_acc();
        }

        if (st >= 1) asm volatile("cp.async.wait_group 0;" ::: "memory");
        __syncthreads();                    // act + dens visible, weights resident

        if (st == 7 && half == 0 && m == 0) {   // combine density halves
#pragma unroll
            for (int rr = 0; rr < 4; rr++) {
                const int r = row0 + rr * 8;
                ostg[r * 4 + 3] = dens[r] + dens[128 + r];
            }
        }

        if (st == 0 || st == 3)      mma_body.template operator()<4, PSTR>(sptr(posH));
        else if (st == 8)            mma_body.template operator()<2, VSTR>(sptr(viewH));
        else if (st == 10) {                // rgb: K=128, N=8 (3 real), half 0 only
            if (half == 0) {
                float c8a[4] = {0.f, 0.f, 0.f, 0.f};
                float c8b[4] = {0.f, 0.f, 0.f, 0.f};
                const uint32_t abase = ab + (uint32_t)(arowk * ASTR + nsel) * 2;
                const uint32_t wb2 = sb + SM_W + (uint32_t)(krow * WSTR) * 2;
#pragma unroll
                for (int kt = 0; kt < 8; kt++) {
                    uint32_t ta0[4], ta1[4];
                    const uint32_t ao = abase + (uint32_t)(kt * 16) * 2;
                    ldm4(ta0[0], ta0[1], ta0[2], ta0[3], ao);
                    ldm4(ta1[0], ta1[1], ta1[2], ta1[3], ao + (uint32_t)(16 * ASTR) * 2);
                    uint32_t b0, b1;
                    ldm2t(b0, b1, wb2 + (uint32_t)(kt * 16 * WSTR) * 2);
                    mma_f16(c8a, ta0, b0, b1);
                    mma_f16(c8b, ta1, b0, b1);
                }
                if (2 * m < 3) {
                    ostg[row0 * 4 + 2 * m]        = c8a[0];
                    ostg[(row0 + 8) * 4 + 2 * m]  = c8a[2];
                    ostg[(row0 + 16) * 4 + 2 * m] = c8b[0];
                    ostg[(row0 + 24) * 4 + 2 * m] = c8b[2];
                }
                if (2 * m + 1 < 3) {
                    ostg[row0 * 4 + 2 * m + 1]        = c8a[1];
                    ostg[(row0 + 8) * 4 + 2 * m + 1]  = c8a[3];
                    ostg[(row0 + 16) * 4 + 2 * m + 1] = c8b[1];
                    ostg[(row0 + 24) * 4 + 2 * m + 1] = c8b[3];
                }
            }
        } else                        mma_body.template operator()<8, ASTR>(ab);
    }

    __syncthreads();
    if (tid < TILE)
        ((float4*)out)[tile * TILE + tid] = ((const float4*)ostg)[tid];
}

extern "C" void kernel_launch(void* const* d_in, const int* in_sizes, int n_in,
                              void* d_out, int out_size) {
    const float* x     = (const float*)d_in[0];
    const float* d1_W0 = (const float*)d_in[1];
    const float* d1_W1 = (const float*)d_in[2];
    const float* d1_W2 = (const float*)d_in[3];
    const float* d2_W0 = (const float*)d_in[4];
    const float* d2_W1 = (const float*)d_in[5];
    const float* d2_W2 = (const float*)d_in[6];
    const float* d2_W3 = (const float*)d_in[7];
    const float* c_W0  = (const float*)d_in[8];
    const float* c_W1  = (const float*)d_in[9];
    const int N = in_sizes[0] / 90;

    prep_kernel<<<1184, WSTR>>>(d1_W0, d1_W1, d1_W2, d2_W0, d2_W1, d2_W2, d2_W3, c_W0, c_W1);
    cudaFuncSetAttribute(nerf_main, cudaFuncAttributeMaxDynamicSharedMemorySize, SMEM_TOTAL);
    nerf_main<<<N / TILE, TPB, SMEM_TOTAL>>>(x, (float*)d_out);
}

// round 17
// speedup vs baseline: 1.8155x; 1.1340x over previous
#include <cuda_runtime.h>
#include <cuda_fp16.h>
#include <cstdint>

#define TPB  256
#define TILE 128
#define WSTR 136   // weight smem row stride (elems), 128 cols padded
#define PSTR 72    // pos row stride (64 cols padded)
#define VSTR 40    // view row stride (32 cols padded)
#define WBUF 34816 // one stage weight buffer bytes

// Single-fp16 weight scratch, row-major [1184][136], filled by prep kernel.
// Stage rows:  0 d1_W0(0,64)  1 d1_W1(64,128)  2 d1_W2(192,128)
//  3 d2_W0a(320,64)  4 d2_W0b(384,128)  5 d2_W1(512,128)  6 d2_W2(640,128)
//  7 d2_W3f(768,128) 8 c_W0a(896,32)   9 c_W0b(928,128) 10 c_W1p(1056,128)
__device__ __half g_w[1184 * WSTR];
__device__ float g_wd[128];

__constant__ int c_offs[11] = {0, 64, 192, 320, 384, 512, 640, 768, 896, 928, 1056};
__constant__ int c_rows[11] = {64, 128, 128, 64, 128, 128, 128, 128, 32, 128, 128};

__global__ void prep_kernel(const float* __restrict__ d1_W0, const float* __restrict__ d1_W1,
                            const float* __restrict__ d1_W2, const float* __restrict__ d2_W0,
                            const float* __restrict__ d2_W1, const float* __restrict__ d2_W2,
                            const float* __restrict__ d2_W3, const float* __restrict__ c_W0,
                            const float* __restrict__ c_W1) {
    int prow = blockIdx.x;      // 0..1183
    int n = threadIdx.x;        // 0..135
    int li = 0;
#pragma unroll
    for (int i = 1; i < 11; i++)
        if (prow >= c_offs[i]) li = i;
    int k = prow - c_offs[li];
    float v = 0.f;
    if (n < 128) {
        switch (li) {
            case 0: if (k < 63) v = d1_W0[k * 128 + n]; break;
            case 1: v = d1_W1[k * 128 + n]; break;
            case 2: v = d1_W2[k * 128 + n]; break;
            case 3: if (k < 63) v = d2_W0[k * 128 + n]; break;
            case 4: v = d2_W0[(63 + k) * 128 + n]; break;
            case 5: v = d2_W1[k * 128 + n]; break;
            case 6: v = d2_W2[k * 128 + n]; break;
            case 7: v = d2_W3[k * 129 + 1 + n]; break;          // feature cols
            case 8: if (k < 27) v = c_W0[k * 128 + n]; break;
            case 9: v = c_W0[(27 + k) * 128 + n]; break;
            case 10: if (n < 3) v = c_W1[k * 3 + n]; break;
        }
    }
    g_w[prow * WSTR + n] = __float2half_rn(v);
    if (prow == 0 && n < 128) g_wd[n] = d2_W3[n * 129];         // density col
}

__device__ __forceinline__ uint32_t sptr(const void* p) {
    return (uint32_t)__cvta_generic_to_shared(p);
}
__device__ __forceinline__ void ldm4(uint32_t& r0, uint32_t& r1, uint32_t& r2, uint32_t& r3, uint32_t a) {
    asm volatile("ldmatrix.sync.aligned.m8n8.x4.shared.b16 {%0,%1,%2,%3}, [%4];"
                 : "=r"(r0), "=r"(r1), "=r"(r2), "=r"(r3) : "r"(a));
}
__device__ __forceinline__ void ldm4t(uint32_t& r0, uint32_t& r1, uint32_t& r2, uint32_t& r3, uint32_t a) {
    asm volatile("ldmatrix.sync.aligned.m8n8.x4.trans.shared.b16 {%0,%1,%2,%3}, [%4];"
                 : "=r"(r0), "=r"(r1), "=r"(r2), "=r"(r3) : "r"(a));
}
__device__ __forceinline__ void ldm2t(uint32_t& r0, uint32_t& r1, uint32_t a) {
    asm volatile("ldmatrix.sync.aligned.m8n8.x2.trans.shared.b16 {%0,%1}, [%2];"
                 : "=r"(r0), "=r"(r1) : "r"(a));
}
__device__ __forceinline__ void mma_f16(float* c, const uint32_t* a, uint32_t b0, uint32_t b1) {
    asm volatile("mma.sync.aligned.m16n8k16.row.col.f32.f16.f16.f32 "
                 "{%0,%1,%2,%3}, {%4,%5,%6,%7}, {%8,%9}, {%0,%1,%2,%3};"
                 : "+f"(c[0]), "+f"(c[1]), "+f"(c[2]), "+f"(c[3])
                 : "r"(a[0]), "r"(a[1]), "r"(a[2]), "r"(a[3]), "r"(b0), "r"(b1));
}
__device__ __forceinline__ void cpa16cg(uint32_t s, const void* g) {
    asm volatile("cp.async.cg.shared.global [%0], [%1], 16;" :: "r"(s), "l"(g));
}
__device__ __forceinline__ void mbar_wait(uint32_t mbar, uint32_t parity) {
    uint32_t done;
    asm volatile("{\n\t.reg .pred p;\n\t"
                 "mbarrier.try_wait.parity.acquire.cta.shared::cta.b64 p, [%1], %2;\n\t"
                 "selp.b32 %0, 1, 0, p;\n\t}"
                 : "=r"(done) : "r"(mbar), "r"(parity) : "memory");
    if (!done) {
        asm volatile("{\n\t.reg .pred P1;\n\t"
                     "WL_%=:\n\t"
                     "mbarrier.try_wait.parity.acquire.cta.shared::cta.b64 P1, [%0], %1, 0x989680;\n\t"
                     "@P1 bra.uni WD_%=;\n\t"
                     "bra.uni WL_%=;\n\t"
                     "WD_%=:\n\t}"
                     :: "r"(mbar), "r"(parity) : "memory");
    }
}

// -------- SMEM map (bytes): double-buffered weights, register activations --------
#define SM_W0    0                       // 34816
#define SM_W1    34816                   // 34816
#define SM_POS   69632                   // 128 x 72 x fp16 = 18432
#define SM_VIEW  88064                   // 128 x 40 x fp16 = 10240
#define SM_WD    98304                   // 128 f32 = 512
#define SM_OSTG  98816                   // 128 x 4 f32 = 2048
#define SM_MBAR  100864                  // full0,full1,cons0,cons1 (4 x 8B)
#define SMEM_TOTAL 100928

__global__ void __launch_bounds__(TPB, 2)
nerf_main(const float* __restrict__ x, float* __restrict__ out) {
    extern __shared__ __align__(16) char smem[];
    const uint32_t sb = sptr(smem);
    __half* posH  = (__half*)(smem + SM_POS);
    __half* viewH = (__half*)(smem + SM_VIEW);
    float* swd  = (float*)(smem + SM_WD);
    float* ostg = (float*)(smem + SM_OSTG);
    const uint32_t mfull = sb + SM_MBAR;        // +0, +8
    const uint32_t mcons = sb + SM_MBAR + 16;   // +0, +8

    const int tid  = threadIdx.x;
    const int lane = tid & 31;
    const int warp = tid >> 5;
    const int r0   = warp * 16;
    const size_t tile = blockIdx.x;

    if (tid == 0) {
        asm volatile("mbarrier.init.shared.b64 [%0], %1;" :: "r"(mfull),      "r"(TPB) : "memory");
        asm volatile("mbarrier.init.shared.b64 [%0], %1;" :: "r"(mfull + 8),  "r"(TPB) : "memory");
        asm volatile("mbarrier.init.shared.b64 [%0], %1;" :: "r"(mcons),      "r"(TPB) : "memory");
        asm volatile("mbarrier.init.shared.b64 [%0], %1;" :: "r"(mcons + 8),  "r"(TPB) : "memory");
    }
    __syncthreads();

    auto loadW = [&](int st) {                  // issue this thread's slice into buf st&1
        const uint32_t b = sb + ((st & 1) ? SM_W1 : SM_W0);
        const __half* g = g_w + c_offs[st] * WSTR;
        const int chunks = c_rows[st] * 17;     // 16B chunks
        for (int i = tid; i < chunks; i += TPB)
            cpa16cg(b + i * 16, g + i * 8);
    };
    auto arriveFull = [&](int st) {
        asm volatile("cp.async.mbarrier.arrive.noinc.shared.b64 [%0];"
                     :: "r"(mfull + (uint32_t)(st & 1) * 8) : "memory");
    };

    // prologue: stages 0 and 1 weights in flight
    loadW(0); arriveFull(0);
    loadW(1); arriveFull(1);

    // zero pos/view buffers (padded cols must be 0), load density weights, stage x
    {
        uint4* pz = (uint4*)(smem + SM_POS);
        for (int i = tid; i < (SM_WD - SM_POS) / 16; i += TPB)
            pz[i] = make_uint4(0, 0, 0, 0);
        if (tid < 128) swd[tid] = g_wd[tid];
    }
    __syncthreads();
    {
        const float* xt = x + tile * (size_t)(TILE * 90);
        for (int i = tid; i < TILE * 90; i += TPB) {
            int row = i / 90, c = i - row * 90;
            __half h = __float2half_rn(xt[i]);
            if (c < 63) posH[row * PSTR + c] = h;
            else        viewH[row * VSTR + c - 63] = h;
        }
    }
    __syncthreads();                            // pos/view visible to all warps

    float acc[16][4];                           // M=16 rows x N=128 cols (16 n8 tiles)
    uint32_t aH[8][4];                          // K=128 A fragments (own rows)
    const int krow = lane & 15;
    const int nsel = (lane >> 4) * 8;
    const int rq = lane >> 2, m = lane & 3;
    const int row0 = r0 + rq;

    auto zero_acc = [&]() {
#pragma unroll
        for (int t = 0; t < 16; t++)
#pragma unroll
            for (int j = 0; j < 4; j++) acc[t][j] = 0.f;
    };
    // accumulators -> next-layer A fragments (single fp16), pure registers
    auto split_frags = [&](bool dorelu) {
#pragma unroll
        for (int kt = 0; kt < 8; kt++)
#pragma unroll
            for (int h = 0; h < 2; h++)
#pragma unroll
                for (int p = 0; p < 2; p++) {
                    float v0 = acc[2 * kt + h][2 * p];
                    float v1 = acc[2 * kt + h][2 * p + 1];
                    if (dorelu) { v0 = fmaxf(v0, 0.f); v1 = fmaxf(v1, 0.f); }
                    __half2 hh = __floats2half2_rn(v0, v1);
                    aH[kt][h * 2 + p] = reinterpret_cast<uint32_t&>(hh);
                }
    };
    // A from smem (pos/view)
    auto mma_smem = [&](const __half* AH, int astr, int KT, uint32_t wb) {
        uint32_t bH = sptr(AH);
        int arow = r0 + (lane & 15);
        int acol = (lane >> 4) * 8;
        for (int kt = 0; kt < KT; kt++) {
            uint32_t ta[4];
            uint32_t ao = (uint32_t)(arow * astr + kt * 16 + acol) * 2;
            ldm4(ta[0], ta[1], ta[2], ta[3], bH + ao);
#pragma unroll
            for (int np = 0; np < 8; np++) {
                uint32_t b0, b1, b2, b3;
                uint32_t wo = (uint32_t)((kt * 16 + krow) * WSTR + np * 16 + nsel) * 2;
                ldm4t(b0, b1, b2, b3, wb + wo);
                mma_f16(acc[2 * np], ta, b0, b1);
                mma_f16(acc[2 * np + 1], ta, b2, b3);
            }
        }
    };
    // A from register fragments, K=128
    auto mma_reg = [&](uint32_t wb) {
#pragma unroll
        for (int kt = 0; kt < 8; kt++)
#pragma unroll
            for (int np = 0; np < 8; np++) {
                uint32_t b0, b1, b2, b3;
                uint32_t wo = (uint32_t)((kt * 16 + krow) * WSTR + np * 16 + nsel) * 2;
                ldm4t(b0, b1, b2, b3, wb + wo);
                mma_f16(acc[2 * np], aH[kt], b0, b1);
                mma_f16(acc[2 * np + 1], aH[kt], b2, b3);
            }
    };

    zero_acc();
    for (int st = 0; st < 11; st++) {
        const uint32_t p = (uint32_t)(st >> 1) & 1;
        const uint32_t boff = (uint32_t)(st & 1) * 8;

        // ---- stage-boundary register work on PREVIOUS acc (no barrier) ----
        if (st == 7) {                          // density from relu'd h5 (own 16 rows)
#pragma unroll
            for (int t = 0; t < 16; t++)
#pragma unroll
                for (int j = 0; j < 4; j++) acc[t][j] = fmaxf(acc[t][j], 0.f);
            float d0 = 0.f, d1 = 0.f;
#pragma unroll
            for (int t = 0; t < 16; t++) {
                float w0 = swd[8 * t + 2 * m], w1 = swd[8 * t + 2 * m + 1];
                d0 += acc[t][0] * w0 + acc[t][1] * w1;
                d1 += acc[t][2] * w0 + acc[t][3] * w1;
            }
            d0 += __shfl_xor_sync(~0u, d0, 1); d0 += __shfl_xor_sync(~0u, d0, 2);
            d1 += __shfl_xor_sync(~0u, d1, 1); d1 += __shfl_xor_sync(~0u, d1, 2);
            if (m == 0) { ostg[row0 * 4 + 3] = d0; ostg[(row0 + 8) * 4 + 3] = d1; }
        }
        if (st >= 1 && st != 4 && st != 9) {
            split_frags(st <= 6 || st == 10);   // relu except feature path (st7 pre-relu'd)
            if (st != 10) zero_acc();
        }

        // ---- wait for this stage's weights (mbarrier, warps drift freely) ----
        mbar_wait(mfull + boff, p);

        const uint32_t wb = sb + ((st & 1) ? SM_W1 : SM_W0);
        if (st == 0 || st == 3)      mma_smem(posH, PSTR, 4, wb);
        else if (st == 8)            mma_smem(viewH, VSTR, 2, wb);
        else if (st == 10) {                    // rgb: K=128, N=8 (3 real)
            float c8[4] = {0.f, 0.f, 0.f, 0.f};
#pragma unroll
            for (int kt = 0; kt < 8; kt++) {
                uint32_t b0, b1;
                uint32_t wo = (uint32_t)((kt * 16 + krow) * WSTR) * 2;
                ldm2t(b0, b1, wb + wo);
                mma_f16(c8, aH[kt], b0, b1);
            }
            if (2 * m < 3)     { ostg[row0 * 4 + 2 * m] = c8[0];     ostg[(row0 + 8) * 4 + 2 * m] = c8[2]; }
            if (2 * m + 1 < 3) { ostg[row0 * 4 + 2 * m + 1] = c8[1]; ostg[(row0 + 8) * 4 + 2 * m + 1] = c8[3]; }
        } else                        mma_reg(wb);

        // ---- signal done with this buffer; produce stage st+2 into it ----
        asm volatile("mbarrier.arrive.shared.b64 _, [%0];" :: "r"(mcons + boff) : "memory");
        if (st + 2 <= 10) {
            mbar_wait(mcons + boff, p);         // all warps done reading buf st&1
            loadW(st + 2);
            arriveFull(st + 2);
        }
    }

    __syncthreads();
    if (tid < TILE)
        ((float4*)out)[tile * TILE + tid] = ((const float4*)ostg)[tid];
}

extern "C" void kernel_launch(void* const* d_in, const int* in_sizes, int n_in,
                              void* d_out, int out_size) {
    const float* x     = (const float*)d_in[0];
    const float* d1_W0 = (const float*)d_in[1];
    const float* d1_W1 = (const float*)d_in[2];
    const float* d1_W2 = (const float*)d_in[3];
    const float* d2_W0 = (const float*)d_in[4];
    const float* d2_W1 = (const float*)d_in[5];
    const float* d2_W2 = (const float*)d_in[6];
    const float* d2_W3 = (const float*)d_in[7];
    const float* c_W0  = (const float*)d_in[8];
    const float* c_W1  = (const float*)d_in[9];
    const int N = in_sizes[0] / 90;

    prep_kernel<<<1184, WSTR>>>(d1_W0, d1_W1, d1_W2, d2_W0, d2_W1, d2_W2, d2_W3, c_W0, c_W1);
    cudaFuncSetAttribute(nerf_main, cudaFuncAttributeMaxDynamicSharedMemorySize, SMEM_TOTAL);
    nerf_main<<<N / TILE, TPB, SMEM_TOTAL>>>(x, (float*)d_out);
}